// round 6
// baseline (speedup 1.0000x reference)
#include <cuda_runtime.h>
#include <cuda_bf16.h>
#include <math.h>
#include <stdint.h>

#define B_N    8192
#define K_N    512
#define D_N    2048
#define Q_N    8
#define LOG2PI 1.8378770664093453f
#define EPSC   1e-5f

// ---------------- scratch (static __device__, no allocation) ----------------
__device__ __nv_bfloat16 g_XB[(size_t)B_N * D_N];   // X in bf16
__device__ __nv_bfloat16 g_WB[(size_t)4608 * D_N];  // [512 pm | 4096 PinvW] x D, bf16
__device__ float         g_T [(size_t)B_N * K_N];   // t1[b][k], 16 MB
__device__ __nv_bfloat16 g_V [(size_t)B_N * 4096];  // v GEMM out (pre-subtract), bf16, 64 MB
__device__ float  g_psi_inv[D_N];
__device__ float  g_logdetPsi;
__device__ float  g_r[B_N];
__device__ float  g_alpha[K_N * 8];
__device__ float  g_Sacc[K_N * 45];
__device__ float  g_wpm[K_N * 8];
__device__ float  g_Minv[K_N * 64];                 // 0.5 * M^-1 (0.5 folded in)
__device__ float  g_logdetM[K_N];
__device__ float  g_mumu[K_N];
__device__ float  g_off[K_N];
__device__ double g_acc;

__device__ __forceinline__ float softplusf(float x) {
    return x > 20.0f ? x : log1pf(expf(x));
}
__device__ __forceinline__ uint32_t smem_u32(const void* p) {
    uint32_t a;
    asm("{ .reg .u64 t; cvta.to.shared.u64 t, %1; cvt.u32.u64 %0, t; }" : "=r"(a) : "l"(p));
    return a;
}
__device__ __forceinline__ void cp_async16(uint32_t saddr, const void* gaddr) {
    asm volatile("cp.async.cg.shared.global [%0], [%1], 16;" :: "r"(saddr), "l"(gaddr));
}

// ---------------- psi precompute ----------------
__global__ void k_psi(const float* __restrict__ psi_rho) {
    __shared__ float ssum;
    int tid = threadIdx.x;
    if (tid == 0) ssum = 0.0f;
    __syncthreads();
    float l = 0.0f;
    for (int d = tid; d < D_N; d += 256) {
        float p = softplusf(psi_rho[d]) + EPSC;
        g_psi_inv[d] = 1.0f / p;
        l += logf(p);
    }
    atomicAdd(&ssum, l);
    __syncthreads();
    if (tid == 0) g_logdetPsi = ssum;
}

// ---------------- X -> bf16 ----------------
__global__ void k_cvt(const float* __restrict__ x) {
    size_t i = ((size_t)blockIdx.x * 256 + threadIdx.x) * 8;
    float4 a = *(const float4*)(x + i);
    float4 b = *(const float4*)(x + i + 4);
    __nv_bfloat162 p0 = __float22bfloat162_rn(make_float2(a.x, a.y));
    __nv_bfloat162 p1 = __float22bfloat162_rn(make_float2(a.z, a.w));
    __nv_bfloat162 p2 = __float22bfloat162_rn(make_float2(b.x, b.y));
    __nv_bfloat162 p3 = __float22bfloat162_rn(make_float2(b.z, b.w));
    uint4 o;
    o.x = *(uint32_t*)&p0; o.y = *(uint32_t*)&p1;
    o.z = *(uint32_t*)&p2; o.w = *(uint32_t*)&p3;
    *(uint4*)(g_XB + i) = o;
}

// ---------------- pA: column norms -> alpha; zero Sacc ----------------
__global__ void pA(const float* __restrict__ dir_raw,
                   const float* __restrict__ scale_rho) {
    int k = blockIdx.x, tid = threadIdx.x;
    __shared__ float s_nsq[8];
    if (tid < 8)  s_nsq[tid] = 0.0f;
    if (tid < 45) g_Sacc[k * 45 + tid] = 0.0f;
    __syncthreads();
    const float* dirk = dir_raw + (size_t)k * D_N * Q_N;
    float ns[8];
#pragma unroll
    for (int j = 0; j < 8; j++) ns[j] = 0.0f;
    for (int d = tid; d < D_N; d += 256) {
        float4 a  = *(const float4*)(dirk + (size_t)d * 8);
        float4 b4 = *(const float4*)(dirk + (size_t)d * 8 + 4);
        ns[0] += a.x * a.x;  ns[1] += a.y * a.y;
        ns[2] += a.z * a.z;  ns[3] += a.w * a.w;
        ns[4] += b4.x * b4.x; ns[5] += b4.y * b4.y;
        ns[6] += b4.z * b4.z; ns[7] += b4.w * b4.w;
    }
#pragma unroll
    for (int j = 0; j < 8; j++) atomicAdd(&s_nsq[j], ns[j]);
    __syncthreads();
    if (tid < 8) {
        float sp = softplusf(scale_rho[k * 8 + tid]);
        g_alpha[k * 8 + tid] = sp / fmaxf(sqrtf(s_nsq[tid]), EPSC);
    }
}

// ---------------- pB: S/wm/mumu partials + Wcat writes (4-way D split) ------
__global__ void pB(const float* __restrict__ dir_raw,
                   const float* __restrict__ mu) {
    int k = blockIdx.y, chunk = blockIdx.x, tid = threadIdx.x;
    __shared__ float s_acc[45];
    if (tid < 45) s_acc[tid] = 0.0f;
    __syncthreads();

    const float* dirk = dir_raw + (size_t)k * D_N * Q_N;
    const float* muk  = mu + (size_t)k * D_N;
    float al[8];
#pragma unroll
    for (int j = 0; j < 8; j++) al[j] = g_alpha[k * 8 + j];

    float S[36], wm[8], mm = 0.0f;
#pragma unroll
    for (int i = 0; i < 36; i++) S[i] = 0.0f;
#pragma unroll
    for (int i = 0; i < 8; i++) wm[i] = 0.0f;

    int d0 = chunk * 512;
#pragma unroll
    for (int it = 0; it < 2; it++) {
        int d = d0 + tid + it * 256;
        float dv[8];
        float4 a  = *(const float4*)(dirk + (size_t)d * 8);
        float4 b4 = *(const float4*)(dirk + (size_t)d * 8 + 4);
        dv[0] = a.x; dv[1] = a.y; dv[2] = a.z; dv[3] = a.w;
        dv[4] = b4.x; dv[5] = b4.y; dv[6] = b4.z; dv[7] = b4.w;
        float pi = g_psi_inv[d];
        float m  = muk[d];
        float pim = pi * m;
        mm += m * pim;
        int idx = 0;
#pragma unroll
        for (int i = 0; i < 8; i++) {
            float pdi = pi * dv[i];
            wm[i] += m * pdi;
#pragma unroll
            for (int j = 0; j <= i; j++) S[idx++] += pdi * dv[j];
        }
        g_WB[(size_t)k * D_N + d] = __float2bfloat16(pim);
#pragma unroll
        for (int j = 0; j < 8; j++)
            g_WB[(size_t)(K_N + k * 8 + j) * D_N + d] = __float2bfloat16(pi * al[j] * dv[j]);
    }
#pragma unroll
    for (int i = 0; i < 36; i++) atomicAdd(&s_acc[i], S[i]);
#pragma unroll
    for (int j = 0; j < 8; j++) atomicAdd(&s_acc[36 + j], wm[j]);
    atomicAdd(&s_acc[44], mm);
    __syncthreads();
    if (tid < 45) atomicAdd(&g_Sacc[k * 45 + tid], s_acc[tid]);
}

// ---------------- pC: per-k Cholesky / inverse (one thread per k) -----------
__global__ void pC() {
    int k = blockIdx.x * 128 + threadIdx.x;
    if (k >= K_N) return;
    float al[8], acc45[45];
#pragma unroll
    for (int j = 0; j < 8; j++) al[j] = g_alpha[k * 8 + j];
    for (int i = 0; i < 45; i++) acc45[i] = g_Sacc[k * 45 + i];

    float Mm[8][8];
    int idx = 0;
    for (int i = 0; i < 8; i++)
        for (int j = 0; j <= i; j++)
            Mm[i][j] = al[i] * al[j] * acc45[idx++] + (i == j ? 1.0f : 0.0f);
    for (int i = 0; i < 8; i++) {
        for (int j = 0; j <= i; j++) {
            float s = Mm[i][j];
            for (int p = 0; p < j; p++) s -= Mm[i][p] * Mm[j][p];
            if (i == j) Mm[i][i] = sqrtf(s);
            else        Mm[i][j] = s / Mm[j][j];
        }
    }
    float ld = 0.0f;
    for (int i = 0; i < 8; i++) ld += logf(Mm[i][i]);
    g_logdetM[k] = 2.0f * ld;
    g_mumu[k]    = acc45[44];
    for (int j = 0; j < 8; j++) g_wpm[k * 8 + j] = al[j] * acc45[36 + j];

    float Li[8][8];
    for (int i = 0; i < 8; i++)
        for (int j = 0; j < 8; j++) Li[i][j] = 0.0f;
    for (int c = 0; c < 8; c++) {
        for (int i = c; i < 8; i++) {
            float s = (i == c) ? 1.0f : 0.0f;
            for (int p = c; p < i; p++) s -= Mm[i][p] * Li[p][c];
            Li[i][c] = s / Mm[i][i];
        }
    }
    for (int i = 0; i < 8; i++)
        for (int j = 0; j < 8; j++) {
            float s = 0.0f;
            for (int m2 = 0; m2 < 8; m2++) s += Li[m2][i] * Li[m2][j];
            g_Minv[(size_t)k * 64 + i * 8 + j] = 0.5f * s;
        }
}

// ---------------- per-k offset ----------------
__global__ void k_off(const float* __restrict__ pi_logits) {
    __shared__ float buf[512];
    int t = threadIdx.x;
    float v = pi_logits[t];
    buf[t] = v;
    __syncthreads();
    for (int s = 256; s > 0; s >>= 1) {
        if (t < s) buf[t] = fmaxf(buf[t], buf[t + s]);
        __syncthreads();
    }
    float mx = buf[0];
    __syncthreads();
    buf[t] = expf(v - mx);
    __syncthreads();
    for (int s = 256; s > 0; s >>= 1) {
        if (t < s) buf[t] += buf[t + s];
        __syncthreads();
    }
    float lse = logf(buf[0]) + mx;
    g_off[t] = -0.5f * ((float)D_N * LOG2PI + g_logdetPsi + g_logdetM[t] + g_mumu[t])
               + v - lse;
}

// ---------------- r[b] = x^T Psi^-1 x ----------------
__global__ void k_xpx(const float* __restrict__ x) {
    int warp = threadIdx.x >> 5, lane = threadIdx.x & 31;
    int b = blockIdx.x * 8 + warp;
    const float* xb = x + (size_t)b * D_N;
    float s = 0.0f;
    for (int d = lane * 4; d < D_N; d += 128) {
        float4 xv = *(const float4*)(xb + d);
        float4 pv = *(const float4*)(g_psi_inv + d);
        s += xv.x * xv.x * pv.x + xv.y * xv.y * pv.y
           + xv.z * xv.z * pv.z + xv.w * xv.w * pv.w;
    }
    for (int o = 16; o; o >>= 1) s += __shfl_xor_sync(0xffffffffu, s, o);
    if (lane == 0) g_r[b] = s;
}

// ---------------- bf16 MMA GEMM (round-3 mainloop, light epilogue) ----------
#define BK       32
#define KBLOCKS  (D_N / BK)      // 64
#define STAGES   3
#define TILE_A   8192
#define TILE_B   8192
#define TILE_AB  (TILE_A + TILE_B)

__global__ void __launch_bounds__(256, 2) k_mma_gemm() {
    __shared__ __align__(128) char smem[STAGES * TILE_AB];
    const int tid  = threadIdx.x;
    const int wid  = tid >> 5;
    const int lane = tid & 31;
    const int warp_m = wid & 1;    // 2 x 64 rows
    const int warp_n = wid >> 1;   // 4 x 32 cols
    const int bx = blockIdx.x;     // 0..35 (bx<4 -> t1 region, else v region)
    const int by = blockIdx.y;     // 0..63

    const uint32_t sbase = smem_u32(smem);
    const __nv_bfloat16* Ag = g_XB + (size_t)(by * 128) * D_N;
    const __nv_bfloat16* Bg = g_WB + (size_t)(bx * 128) * D_N;

    auto load_stage = [&](int s, int kb) {
        uint32_t aB = sbase + s * TILE_AB;
        uint32_t bB = aB + TILE_A;
#pragma unroll
        for (int i = 0; i < 2; i++) {
            int id  = tid + i * 256;
            int row = id >> 2;
            int ch  = id & 3;
            int sw  = ch ^ ((row >> 1) & 3);
            cp_async16(aB + row * 64 + sw * 16, Ag + (size_t)row * D_N + kb * BK + ch * 8);
            cp_async16(bB + row * 64 + sw * 16, Bg + (size_t)row * D_N + kb * BK + ch * 8);
        }
        asm volatile("cp.async.commit_group;");
    };

    float acc[4][4][4];
#pragma unroll
    for (int mi = 0; mi < 4; mi++)
#pragma unroll
        for (int ni = 0; ni < 4; ni++)
#pragma unroll
            for (int j = 0; j < 4; j++) acc[mi][ni][j] = 0.0f;

    load_stage(0, 0);
    load_stage(1, 1);
    load_stage(2, 2);

    for (int kb = 0; kb < KBLOCKS; kb++) {
        if (kb + 2 < KBLOCKS)       asm volatile("cp.async.wait_group 2;");
        else if (kb + 2 == KBLOCKS) asm volatile("cp.async.wait_group 1;");
        else                        asm volatile("cp.async.wait_group 0;");
        __syncthreads();
        uint32_t aB = sbase + (kb % STAGES) * TILE_AB;
        uint32_t bB = aB + TILE_A;
#pragma unroll
        for (int ks = 0; ks < 2; ks++) {
            uint32_t a[4][4], b[4][2];
#pragma unroll
            for (int mi = 0; mi < 4; mi++) {
                int r  = warp_m * 64 + mi * 16 + (lane & 15);
                int ch = ks * 2 + (lane >> 4);
                uint32_t ad = aB + r * 64 + ((ch ^ ((r >> 1) & 3)) << 4);
                asm volatile("ldmatrix.sync.aligned.m8n8.x4.shared.b16 {%0,%1,%2,%3}, [%4];"
                             : "=r"(a[mi][0]), "=r"(a[mi][1]), "=r"(a[mi][2]), "=r"(a[mi][3])
                             : "r"(ad));
            }
            int c = lane & 15;
#pragma unroll
            for (int ni = 0; ni < 4; ni++) {
                int r  = warp_n * 32 + ni * 8 + (c & 7);
                int ch = ks * 2 + (c >> 3);
                uint32_t bd = bB + r * 64 + ((ch ^ ((r >> 1) & 3)) << 4);
                asm volatile("ldmatrix.sync.aligned.m8n8.x2.shared.b16 {%0,%1}, [%2];"
                             : "=r"(b[ni][0]), "=r"(b[ni][1]) : "r"(bd));
            }
#pragma unroll
            for (int mi = 0; mi < 4; mi++)
#pragma unroll
                for (int ni = 0; ni < 4; ni++) {
                    asm volatile(
                        "mma.sync.aligned.m16n8k16.row.col.f32.bf16.bf16.f32 "
                        "{%0,%1,%2,%3}, {%4,%5,%6,%7}, {%8,%9}, {%0,%1,%2,%3};"
                        : "+f"(acc[mi][ni][0]), "+f"(acc[mi][ni][1]),
                          "+f"(acc[mi][ni][2]), "+f"(acc[mi][ni][3])
                        : "r"(a[mi][0]), "r"(a[mi][1]), "r"(a[mi][2]), "r"(a[mi][3]),
                          "r"(b[ni][0]), "r"(b[ni][1]));
                }
        }
        __syncthreads();
        if (kb + 3 < KBLOCKS) load_stage((kb + 3) % STAGES, kb + 3);
    }

    const int gq = lane >> 2;   // 0..7
    const int tg = lane & 3;    // 0..3

    if (bx < 4) {
        // t1 region: fp32 to g_T
#pragma unroll
        for (int mi = 0; mi < 4; mi++) {
            int r0 = by * 128 + warp_m * 64 + mi * 16 + gq;
            int r1 = r0 + 8;
#pragma unroll
            for (int ni = 0; ni < 4; ni++) {
                int col = bx * 128 + warp_n * 32 + ni * 8 + tg * 2;
                *(float2*)&g_T[(size_t)r0 * K_N + col] = make_float2(acc[mi][ni][0], acc[mi][ni][1]);
                *(float2*)&g_T[(size_t)r1 * K_N + col] = make_float2(acc[mi][ni][2], acc[mi][ni][3]);
            }
        }
    } else {
        // v region: bf16 to g_V
#pragma unroll
        for (int mi = 0; mi < 4; mi++) {
            int r0 = by * 128 + warp_m * 64 + mi * 16 + gq;
            int r1 = r0 + 8;
#pragma unroll
            for (int ni = 0; ni < 4; ni++) {
                int col = (bx - 4) * 128 + warp_n * 32 + ni * 8 + tg * 2;
                __nv_bfloat162 lo = __float22bfloat162_rn(make_float2(acc[mi][ni][0], acc[mi][ni][1]));
                __nv_bfloat162 hi = __float22bfloat162_rn(make_float2(acc[mi][ni][2], acc[mi][ni][3]));
                *(__nv_bfloat162*)&g_V[(size_t)r0 * 4096 + col] = lo;
                *(__nv_bfloat162*)&g_V[(size_t)r1 * 4096 + col] = hi;
            }
        }
    }
}

// ---------------- fused e1+e2: quad + logsumexp + NLL -----------------------
__global__ void __launch_bounds__(256) k_e2() {
    __shared__ float sM[64 * 65];
    __shared__ float sW[64 * 9];
    __shared__ float sO[64];
    int tid = threadIdx.x, warp = tid >> 5, lane = tid & 31;
    int b = blockIdx.x * 8 + warp;
    const __nv_bfloat16* vrow = g_V + (size_t)b * 4096;
    const float* trow = g_T + (size_t)b * K_N;

    float m = -1e30f, s = 0.0f;
    for (int ch = 0; ch < 8; ch++) {
        int k0 = ch * 64;
        for (int t = tid; t < 64 * 64; t += 256)
            sM[(t >> 6) * 65 + (t & 63)] = g_Minv[(size_t)(k0 + (t >> 6)) * 64 + (t & 63)];
        for (int t = tid; t < 512; t += 256)
            sW[(t >> 3) * 9 + (t & 7)] = g_wpm[(k0 + (t >> 3)) * 8 + (t & 7)];
        if (tid < 64) sO[tid] = g_off[k0 + tid];
        __syncthreads();
#pragma unroll
        for (int half = 0; half < 2; half++) {
            int kl = half * 32 + lane;
            int k  = k0 + kl;
            uint4 raw = *(const uint4*)(vrow + (size_t)k * 8);
            float v[8];
            {
                __nv_bfloat162 h0 = *(__nv_bfloat162*)&raw.x;
                __nv_bfloat162 h1 = *(__nv_bfloat162*)&raw.y;
                __nv_bfloat162 h2 = *(__nv_bfloat162*)&raw.z;
                __nv_bfloat162 h3 = *(__nv_bfloat162*)&raw.w;
                float2 f0 = __bfloat1622float2(h0);
                float2 f1 = __bfloat1622float2(h1);
                float2 f2 = __bfloat1622float2(h2);
                float2 f3 = __bfloat1622float2(h3);
                v[0] = f0.x; v[1] = f0.y; v[2] = f1.x; v[3] = f1.y;
                v[4] = f2.x; v[5] = f2.y; v[6] = f3.x; v[7] = f3.y;
            }
            const float* Wv = &sW[kl * 9];
#pragma unroll
            for (int j = 0; j < 8; j++) v[j] -= Wv[j];
            const float* Mv = &sM[kl * 65];
            float q = 0.0f;
#pragma unroll
            for (int i = 0; i < 8; i++) {
                float mi = 0.0f;
#pragma unroll
                for (int j = 0; j < 8; j++) mi += Mv[i * 8 + j] * v[j];
                q += v[i] * mi;
            }
            float val = trow[k] + sO[kl] + q;
            // online logsumexp
            if (val > m) { s = s * expf(m - val) + 1.0f; m = val; }
            else         { s += expf(val - m); }
        }
        __syncthreads();
    }
    // warp combine (m, s)
    for (int o = 16; o; o >>= 1) {
        float mo = __shfl_xor_sync(0xffffffffu, m, o);
        float so = __shfl_xor_sync(0xffffffffu, s, o);
        float M = fmaxf(m, mo);
        s = s * expf(m - M) + so * expf(mo - M);
        m = M;
    }
    if (lane == 0) {
        float logp = logf(s) + m - 0.5f * g_r[b];
        atomicAdd(&g_acc, (double)(-logp));
    }
}

__global__ void k_init() { g_acc = 0.0; }
__global__ void k_fin(float* out) { out[0] = (float)(g_acc * (1.0 / (double)B_N)); }

// ---------------- launch ----------------
extern "C" void kernel_launch(void* const* d_in, const int* in_sizes, int n_in,
                              void* d_out, int out_size) {
    const float* x         = (const float*)d_in[0];
    const float* mu        = (const float*)d_in[1];
    const float* dir_raw   = (const float*)d_in[2];
    const float* scale_rho = (const float*)d_in[3];
    const float* psi_rho   = (const float*)d_in[4];
    const float* pi_logits = (const float*)d_in[5];
    float* out = (float*)d_out;

    k_init<<<1, 1>>>();
    k_psi<<<1, 256>>>(psi_rho);
    k_cvt<<<(B_N * D_N) / (256 * 8), 256>>>(x);
    pA<<<K_N, 256>>>(dir_raw, scale_rho);
    pB<<<dim3(4, K_N), 256>>>(dir_raw, mu);
    pC<<<4, 128>>>();
    k_off<<<1, 512>>>(pi_logits);
    k_xpx<<<B_N / 8, 256>>>(x);
    dim3 gg(36, 64);
    k_mma_gemm<<<gg, 256>>>();
    k_e2<<<B_N / 8, 256>>>();
    k_fin<<<1, 1>>>(out);
}

// round 8
// speedup vs baseline: 2.1307x; 2.1307x over previous
#include <cuda_runtime.h>
#include <cuda_bf16.h>
#include <math.h>
#include <stdint.h>

#define B_N    8192
#define K_N    512
#define D_N    2048
#define Q_N    8
#define LOG2PI 1.8378770664093453f
#define EPSC   1e-5f

// ---------------- scratch (static __device__, no allocation) ----------------
__device__ __nv_bfloat16 g_XB[(size_t)B_N * D_N];   // X in bf16
__device__ __nv_bfloat16 g_WB[(size_t)4608 * D_N];  // [512 pm | 4096 PinvW] x D, bf16
__device__ float         g_T [(size_t)B_N * K_N];   // t1[b][k], 16 MB
__device__ __nv_bfloat16 g_V [(size_t)B_N * 4096];  // v GEMM out (pre-subtract), bf16
__device__ float  g_psi_inv[D_N];
__device__ float  g_logdetPsi;
__device__ float  g_r[B_N];
__device__ float  g_alpha[K_N * 8];
__device__ float  g_Sacc[K_N * 45];
__device__ float  g_Lp[K_N * 48];                   // [0..35] sqrt(.5)*Linv, [36..43] wpm, [44] off
__device__ float  g_logdetM[K_N];
__device__ float  g_mumu[K_N];
__device__ double g_acc;

__device__ __forceinline__ float softplusf(float x) {
    return x > 20.0f ? x : log1pf(expf(x));
}
__device__ __forceinline__ uint32_t smem_u32(const void* p) {
    uint32_t a;
    asm("{ .reg .u64 t; cvta.to.shared.u64 t, %1; cvt.u32.u64 %0, t; }" : "=r"(a) : "l"(p));
    return a;
}
__device__ __forceinline__ void cp_async16(uint32_t saddr, const void* gaddr) {
    asm volatile("cp.async.cg.shared.global [%0], [%1], 16;" :: "r"(saddr), "l"(gaddr));
}
__device__ __forceinline__ float warp_sum(float v) {
#pragma unroll
    for (int o = 16; o; o >>= 1) v += __shfl_xor_sync(0xffffffffu, v, o);
    return v;
}

// ---------------- pA: psi (block 0) + column norms -> alpha; zero Sacc ------
__global__ void pA(const float* __restrict__ dir_raw,
                   const float* __restrict__ scale_rho,
                   const float* __restrict__ psi_rho) {
    int k = blockIdx.x, tid = threadIdx.x, lane = tid & 31;
    __shared__ float s_nsq[8];
    __shared__ float s_psis;
    if (tid < 8)  s_nsq[tid] = 0.0f;
    if (tid == 8) s_psis = 0.0f;
    if (tid < 45) g_Sacc[k * 45 + tid] = 0.0f;
    __syncthreads();

    if (k == 0) {
        float l = 0.0f;
        for (int d = tid; d < D_N; d += 256) {
            float p = softplusf(psi_rho[d]) + EPSC;
            g_psi_inv[d] = 1.0f / p;
            l += logf(p);
        }
        l = warp_sum(l);
        if (lane == 0) atomicAdd(&s_psis, l);
    }

    const float* dirk = dir_raw + (size_t)k * D_N * Q_N;
    float ns[8];
#pragma unroll
    for (int j = 0; j < 8; j++) ns[j] = 0.0f;
    for (int d = tid; d < D_N; d += 256) {
        float4 a  = *(const float4*)(dirk + (size_t)d * 8);
        float4 b4 = *(const float4*)(dirk + (size_t)d * 8 + 4);
        ns[0] += a.x * a.x;  ns[1] += a.y * a.y;
        ns[2] += a.z * a.z;  ns[3] += a.w * a.w;
        ns[4] += b4.x * b4.x; ns[5] += b4.y * b4.y;
        ns[6] += b4.z * b4.z; ns[7] += b4.w * b4.w;
    }
#pragma unroll
    for (int j = 0; j < 8; j++) {
        ns[j] = warp_sum(ns[j]);
        if (lane == 0) atomicAdd(&s_nsq[j], ns[j]);
    }
    __syncthreads();
    if (tid < 8) {
        float sp = softplusf(scale_rho[k * 8 + tid]);
        g_alpha[k * 8 + tid] = sp / fmaxf(sqrtf(s_nsq[tid]), EPSC);
    }
    if (k == 0 && tid == 8) g_logdetPsi = s_psis;
}

// ---------------- X -> bf16 ----------------
__global__ void k_cvt(const float* __restrict__ x) {
    size_t i = ((size_t)blockIdx.x * 256 + threadIdx.x) * 8;
    float4 a = *(const float4*)(x + i);
    float4 b = *(const float4*)(x + i + 4);
    __nv_bfloat162 p0 = __float22bfloat162_rn(make_float2(a.x, a.y));
    __nv_bfloat162 p1 = __float22bfloat162_rn(make_float2(a.z, a.w));
    __nv_bfloat162 p2 = __float22bfloat162_rn(make_float2(b.x, b.y));
    __nv_bfloat162 p3 = __float22bfloat162_rn(make_float2(b.z, b.w));
    uint4 o;
    o.x = *(uint32_t*)&p0; o.y = *(uint32_t*)&p1;
    o.z = *(uint32_t*)&p2; o.w = *(uint32_t*)&p3;
    *(uint4*)(g_XB + i) = o;
}

// ---------------- pB: S/wm/mumu partials + Wcat writes (4-way D split) ------
__global__ void pB(const float* __restrict__ dir_raw,
                   const float* __restrict__ mu) {
    int k = blockIdx.y, chunk = blockIdx.x, tid = threadIdx.x, lane = tid & 31;
    __shared__ float s_acc[45];
    if (tid < 45) s_acc[tid] = 0.0f;
    __syncthreads();

    const float* dirk = dir_raw + (size_t)k * D_N * Q_N;
    const float* muk  = mu + (size_t)k * D_N;
    float al[8];
#pragma unroll
    for (int j = 0; j < 8; j++) al[j] = g_alpha[k * 8 + j];

    float S[36], wm[8], mm = 0.0f;
#pragma unroll
    for (int i = 0; i < 36; i++) S[i] = 0.0f;
#pragma unroll
    for (int i = 0; i < 8; i++) wm[i] = 0.0f;

    int d0 = chunk * 512;
#pragma unroll
    for (int it = 0; it < 2; it++) {
        int d = d0 + tid + it * 256;
        float dv[8];
        float4 a  = *(const float4*)(dirk + (size_t)d * 8);
        float4 b4 = *(const float4*)(dirk + (size_t)d * 8 + 4);
        dv[0] = a.x; dv[1] = a.y; dv[2] = a.z; dv[3] = a.w;
        dv[4] = b4.x; dv[5] = b4.y; dv[6] = b4.z; dv[7] = b4.w;
        float pi = g_psi_inv[d];
        float m  = muk[d];
        float pim = pi * m;
        mm += m * pim;
        int idx = 0;
#pragma unroll
        for (int i = 0; i < 8; i++) {
            float pdi = pi * dv[i];
            wm[i] += m * pdi;
#pragma unroll
            for (int j = 0; j <= i; j++) S[idx++] += pdi * dv[j];
        }
        g_WB[(size_t)k * D_N + d] = __float2bfloat16(pim);
#pragma unroll
        for (int j = 0; j < 8; j++)
            g_WB[(size_t)(K_N + k * 8 + j) * D_N + d] = __float2bfloat16(pi * al[j] * dv[j]);
    }
#pragma unroll
    for (int i = 0; i < 36; i++) {
        S[i] = warp_sum(S[i]);
        if (lane == 0) atomicAdd(&s_acc[i], S[i]);
    }
#pragma unroll
    for (int j = 0; j < 8; j++) {
        wm[j] = warp_sum(wm[j]);
        if (lane == 0) atomicAdd(&s_acc[36 + j], wm[j]);
    }
    mm = warp_sum(mm);
    if (lane == 0) atomicAdd(&s_acc[44], mm);
    __syncthreads();
    if (tid < 45) atomicAdd(&g_Sacc[k * 45 + tid], s_acc[tid]);
}

// ---------------- bf16 MMA GEMM (x4 B ldmatrix) -----------------------------
#define BK       32
#define KBLOCKS  (D_N / BK)      // 64
#define STAGES   3
#define TILE_A   8192
#define TILE_B   8192
#define TILE_AB  (TILE_A + TILE_B)

__global__ void __launch_bounds__(256, 2) k_mma_gemm() {
    __shared__ __align__(128) char smem[STAGES * TILE_AB];
    const int tid  = threadIdx.x;
    const int wid  = tid >> 5;
    const int lane = tid & 31;
    const int warp_m = wid & 1;    // 2 x 64 rows
    const int warp_n = wid >> 1;   // 4 x 32 cols
    const int bx = blockIdx.x;     // 0..35 (bx<4 -> t1 region, else v region)
    const int by = blockIdx.y;     // 0..63

    const uint32_t sbase = smem_u32(smem);
    const __nv_bfloat16* Ag = g_XB + (size_t)(by * 128) * D_N;
    const __nv_bfloat16* Bg = g_WB + (size_t)(bx * 128) * D_N;

    auto load_stage = [&](int s, int kb) {
        uint32_t aB = sbase + s * TILE_AB;
        uint32_t bB = aB + TILE_A;
#pragma unroll
        for (int i = 0; i < 2; i++) {
            int id  = tid + i * 256;
            int row = id >> 2;
            int ch  = id & 3;
            int sw  = ch ^ ((row >> 1) & 3);
            cp_async16(aB + row * 64 + sw * 16, Ag + (size_t)row * D_N + kb * BK + ch * 8);
            cp_async16(bB + row * 64 + sw * 16, Bg + (size_t)row * D_N + kb * BK + ch * 8);
        }
        asm volatile("cp.async.commit_group;");
    };

    float acc[4][4][4];
#pragma unroll
    for (int mi = 0; mi < 4; mi++)
#pragma unroll
        for (int ni = 0; ni < 4; ni++)
#pragma unroll
            for (int j = 0; j < 4; j++) acc[mi][ni][j] = 0.0f;

    load_stage(0, 0);
    load_stage(1, 1);
    load_stage(2, 2);

    for (int kb = 0; kb < KBLOCKS; kb++) {
        if (kb + 2 < KBLOCKS)       asm volatile("cp.async.wait_group 2;");
        else if (kb + 2 == KBLOCKS) asm volatile("cp.async.wait_group 1;");
        else                        asm volatile("cp.async.wait_group 0;");
        __syncthreads();
        uint32_t aB = sbase + (kb % STAGES) * TILE_AB;
        uint32_t bB = aB + TILE_A;
#pragma unroll
        for (int ks = 0; ks < 2; ks++) {
            uint32_t a[4][4], b[4][2];
#pragma unroll
            for (int mi = 0; mi < 4; mi++) {
                int r  = warp_m * 64 + mi * 16 + (lane & 15);
                int ch = ks * 2 + (lane >> 4);
                uint32_t ad = aB + r * 64 + ((ch ^ ((r >> 1) & 3)) << 4);
                asm volatile("ldmatrix.sync.aligned.m8n8.x4.shared.b16 {%0,%1,%2,%3}, [%4];"
                             : "=r"(a[mi][0]), "=r"(a[mi][1]), "=r"(a[mi][2]), "=r"(a[mi][3])
                             : "r"(ad));
            }
#pragma unroll
            for (int p = 0; p < 2; p++) {
                int g  = lane >> 3, rl = lane & 7;
                int r  = warp_n * 32 + p * 16 + (g >> 1) * 8 + rl;
                int ch = ks * 2 + (g & 1);
                uint32_t bd = bB + r * 64 + ((ch ^ ((r >> 1) & 3)) << 4);
                asm volatile("ldmatrix.sync.aligned.m8n8.x4.shared.b16 {%0,%1,%2,%3}, [%4];"
                             : "=r"(b[2 * p][0]), "=r"(b[2 * p][1]),
                               "=r"(b[2 * p + 1][0]), "=r"(b[2 * p + 1][1])
                             : "r"(bd));
            }
#pragma unroll
            for (int mi = 0; mi < 4; mi++)
#pragma unroll
                for (int ni = 0; ni < 4; ni++) {
                    asm volatile(
                        "mma.sync.aligned.m16n8k16.row.col.f32.bf16.bf16.f32 "
                        "{%0,%1,%2,%3}, {%4,%5,%6,%7}, {%8,%9}, {%0,%1,%2,%3};"
                        : "+f"(acc[mi][ni][0]), "+f"(acc[mi][ni][1]),
                          "+f"(acc[mi][ni][2]), "+f"(acc[mi][ni][3])
                        : "r"(a[mi][0]), "r"(a[mi][1]), "r"(a[mi][2]), "r"(a[mi][3]),
                          "r"(b[ni][0]), "r"(b[ni][1]));
                }
        }
        __syncthreads();
        if (kb + 3 < KBLOCKS) load_stage((kb + 3) % STAGES, kb + 3);
    }

    const int gq = lane >> 2;
    const int tg = lane & 3;

    if (bx < 4) {
#pragma unroll
        for (int mi = 0; mi < 4; mi++) {
            int r0 = by * 128 + warp_m * 64 + mi * 16 + gq;
            int r1 = r0 + 8;
#pragma unroll
            for (int ni = 0; ni < 4; ni++) {
                int col = bx * 128 + warp_n * 32 + ni * 8 + tg * 2;
                *(float2*)&g_T[(size_t)r0 * K_N + col] = make_float2(acc[mi][ni][0], acc[mi][ni][1]);
                *(float2*)&g_T[(size_t)r1 * K_N + col] = make_float2(acc[mi][ni][2], acc[mi][ni][3]);
            }
        }
    } else {
#pragma unroll
        for (int mi = 0; mi < 4; mi++) {
            int r0 = by * 128 + warp_m * 64 + mi * 16 + gq;
            int r1 = r0 + 8;
#pragma unroll
            for (int ni = 0; ni < 4; ni++) {
                int col = (bx - 4) * 128 + warp_n * 32 + ni * 8 + tg * 2;
                __nv_bfloat162 lo = __float22bfloat162_rn(make_float2(acc[mi][ni][0], acc[mi][ni][1]));
                __nv_bfloat162 hi = __float22bfloat162_rn(make_float2(acc[mi][ni][2], acc[mi][ni][3]));
                *(__nv_bfloat162*)&g_V[(size_t)r0 * 4096 + col] = lo;
                *(__nv_bfloat162*)&g_V[(size_t)r1 * 4096 + col] = hi;
            }
        }
    }
}

// ---------------- pC: per-k Cholesky -> packed sqrt(.5)*Linv + wpm ----------
__global__ void pC() {
    int k = blockIdx.x * 128 + threadIdx.x;
    if (k >= K_N) return;
    float al[8], acc45[45];
#pragma unroll
    for (int j = 0; j < 8; j++) al[j] = g_alpha[k * 8 + j];
    for (int i = 0; i < 45; i++) acc45[i] = g_Sacc[k * 45 + i];

    float Mm[8][8];
    int idx = 0;
    for (int i = 0; i < 8; i++)
        for (int j = 0; j <= i; j++)
            Mm[i][j] = al[i] * al[j] * acc45[idx++] + (i == j ? 1.0f : 0.0f);
    for (int i = 0; i < 8; i++) {
        for (int j = 0; j <= i; j++) {
            float s = Mm[i][j];
            for (int p = 0; p < j; p++) s -= Mm[i][p] * Mm[j][p];
            if (i == j) Mm[i][i] = sqrtf(s);
            else        Mm[i][j] = s / Mm[j][j];
        }
    }
    float ld = 0.0f;
    for (int i = 0; i < 8; i++) ld += logf(Mm[i][i]);
    g_logdetM[k] = 2.0f * ld;
    g_mumu[k]    = acc45[44];
    for (int j = 0; j < 8; j++) g_Lp[k * 48 + 36 + j] = al[j] * acc45[36 + j];

    float Li[8][8];
    for (int i = 0; i < 8; i++)
        for (int j = 0; j < 8; j++) Li[i][j] = 0.0f;
    for (int c = 0; c < 8; c++) {
        for (int i = c; i < 8; i++) {
            float s = (i == c) ? 1.0f : 0.0f;
            for (int p = c; p < i; p++) s -= Mm[i][p] * Li[p][c];
            Li[i][c] = s / Mm[i][i];
        }
    }
    idx = 0;
    for (int i = 0; i < 8; i++)
        for (int j = 0; j <= i; j++)
            g_Lp[k * 48 + idx++] = 0.70710678118654752f * Li[i][j];
}

__global__ void k_init() { g_acc = 0.0; }

// ---------------- per-k offset -> g_Lp[44] ----------------
__global__ void k_off(const float* __restrict__ pi_logits) {
    __shared__ float buf[512];
    int t = threadIdx.x;
    float v = pi_logits[t];
    buf[t] = v;
    __syncthreads();
    for (int s = 256; s > 0; s >>= 1) {
        if (t < s) buf[t] = fmaxf(buf[t], buf[t + s]);
        __syncthreads();
    }
    float mx = buf[0];
    __syncthreads();
    buf[t] = expf(v - mx);
    __syncthreads();
    for (int s = 256; s > 0; s >>= 1) {
        if (t < s) buf[t] += buf[t + s];
        __syncthreads();
    }
    float lse = logf(buf[0]) + mx;
    g_Lp[t * 48 + 44] = -0.5f * ((float)D_N * LOG2PI + g_logdetPsi + g_logdetM[t] + g_mumu[t])
                        + v - lse;
}

// ---------------- r[b] = x^T Psi^-1 x ----------------
__global__ void k_xpx(const float* __restrict__ x) {
    int warp = threadIdx.x >> 5, lane = threadIdx.x & 31;
    int b = blockIdx.x * 8 + warp;
    const float* xb = x + (size_t)b * D_N;
    float s = 0.0f;
    for (int d = lane * 4; d < D_N; d += 128) {
        float4 xv = *(const float4*)(xb + d);
        float4 pv = *(const float4*)(g_psi_inv + d);
        s += xv.x * xv.x * pv.x + xv.y * xv.y * pv.y
           + xv.z * xv.z * pv.z + xv.w * xv.w * pv.w;
    }
    s = warp_sum(s);
    if (lane == 0) g_r[b] = s;
}

// ---------------- fused e1+e2: quad (Cholesky form) + logsumexp + NLL -------
__global__ void __launch_bounds__(256) k_e2() {
    __shared__ float sL[64 * 49];       // packed per-k: 36 Linv + 8 wpm + 1 off (stride 49)
    int tid = threadIdx.x, warp = tid >> 5, lane = tid & 31;
    int b0 = blockIdx.x * 16 + warp * 2;
    int b1 = b0 + 1;
    const __nv_bfloat16* vr0 = g_V + (size_t)b0 * 4096;
    const __nv_bfloat16* vr1 = g_V + (size_t)b1 * 4096;
    const float* tr0 = g_T + (size_t)b0 * K_N;
    const float* tr1 = g_T + (size_t)b1 * K_N;

    float m0 = -1e30f, s0 = 0.0f, m1 = -1e30f, s1 = 0.0f;
    for (int ch = 0; ch < 8; ch++) {
        int k0 = ch * 64;
        for (int t = tid; t < 64 * 48; t += 256) {
            int kk = t / 48, c = t - kk * 48;
            sL[kk * 49 + c] = g_Lp[(size_t)(k0 + kk) * 48 + c];
        }
        __syncthreads();
#pragma unroll
        for (int half = 0; half < 2; half++) {
            int kl = half * 32 + lane;
            int k  = k0 + kl;
            const float* P = &sL[kl * 49];
#pragma unroll
            for (int bb = 0; bb < 2; bb++) {
                const __nv_bfloat16* vrow = bb ? vr1 : vr0;
                const float*          trow = bb ? tr1 : tr0;
                uint4 raw = *(const uint4*)(vrow + (size_t)k * 8);
                float v[8];
                {
                    float2 f0 = __bfloat1622float2(*(__nv_bfloat162*)&raw.x);
                    float2 f1 = __bfloat1622float2(*(__nv_bfloat162*)&raw.y);
                    float2 f2 = __bfloat1622float2(*(__nv_bfloat162*)&raw.z);
                    float2 f3 = __bfloat1622float2(*(__nv_bfloat162*)&raw.w);
                    v[0] = f0.x; v[1] = f0.y; v[2] = f1.x; v[3] = f1.y;
                    v[4] = f2.x; v[5] = f2.y; v[6] = f3.x; v[7] = f3.y;
                }
#pragma unroll
                for (int j = 0; j < 8; j++) v[j] -= P[36 + j];
                float q = 0.0f;
                int idx = 0;
#pragma unroll
                for (int i = 0; i < 8; i++) {
                    float y = 0.0f;
#pragma unroll
                    for (int j = 0; j <= i; j++) y += P[idx++] * v[j];
                    q += y * y;
                }
                float val = trow[k] + P[44] + q;
                if (bb == 0) {
                    if (val > m0) { s0 = s0 * expf(m0 - val) + 1.0f; m0 = val; }
                    else          { s0 += expf(val - m0); }
                } else {
                    if (val > m1) { s1 = s1 * expf(m1 - val) + 1.0f; m1 = val; }
                    else          { s1 += expf(val - m1); }
                }
            }
        }
        __syncthreads();
    }
#pragma unroll
    for (int o = 16; o; o >>= 1) {
        float mo = __shfl_xor_sync(0xffffffffu, m0, o);
        float so = __shfl_xor_sync(0xffffffffu, s0, o);
        float M = fmaxf(m0, mo);
        s0 = s0 * expf(m0 - M) + so * expf(mo - M);
        m0 = M;
        mo = __shfl_xor_sync(0xffffffffu, m1, o);
        so = __shfl_xor_sync(0xffffffffu, s1, o);
        M = fmaxf(m1, mo);
        s1 = s1 * expf(m1 - M) + so * expf(mo - M);
        m1 = M;
    }
    if (lane == 0) {
        float lp = (logf(s0) + m0 - 0.5f * g_r[b0]) + (logf(s1) + m1 - 0.5f * g_r[b1]);
        atomicAdd(&g_acc, (double)(-lp));
    }
}

__global__ void k_fin(float* out) { out[0] = (float)(g_acc * (1.0 / (double)B_N)); }

// ---------------- launch (GEMM is 4th => gets profiled) ----------------
extern "C" void kernel_launch(void* const* d_in, const int* in_sizes, int n_in,
                              void* d_out, int out_size) {
    const float* x         = (const float*)d_in[0];
    const float* mu        = (const float*)d_in[1];
    const float* dir_raw   = (const float*)d_in[2];
    const float* scale_rho = (const float*)d_in[3];
    const float* psi_rho   = (const float*)d_in[4];
    const float* pi_logits = (const float*)d_in[5];
    float* out = (float*)d_out;

    pA<<<K_N, 256>>>(dir_raw, scale_rho, psi_rho);          // 1
    k_cvt<<<(B_N * D_N) / (256 * 8), 256>>>(x);             // 2
    pB<<<dim3(4, K_N), 256>>>(dir_raw, mu);                 // 3
    dim3 gg(36, 64);
    k_mma_gemm<<<gg, 256>>>();                              // 4  <- profiled
    pC<<<4, 128>>>();                                       // 5
    k_init<<<1, 1>>>();                                     // 6
    k_off<<<1, 512>>>(pi_logits);                           // 7
    k_xpx<<<B_N / 8, 256>>>(x);                             // 8
    k_e2<<<B_N / 16, 256>>>();                              // 9
    k_fin<<<1, 1>>>(out);                                   // 10
}

// round 9
// speedup vs baseline: 2.2382x; 1.0505x over previous
#include <cuda_runtime.h>
#include <cuda_bf16.h>
#include <math.h>
#include <stdint.h>

#define B_N    8192
#define K_N    512
#define D_N    2048
#define Q_N    8
#define LOG2PI 1.8378770664093453f
#define EPSC   1e-5f

// ---------------- scratch (static __device__, no allocation) ----------------
__device__ __nv_bfloat16 g_XB[(size_t)B_N * D_N];   // X in bf16
__device__ __nv_bfloat16 g_WB[(size_t)4608 * D_N];  // [512 pm | 4096 pi*dv] x D, bf16 (NO alpha)
__device__ float         g_T [(size_t)B_N * K_N];   // t1[b][k]
__device__ __nv_bfloat16 g_V [(size_t)B_N * 4096];  // vtilde GEMM out, bf16
__device__ float  g_psi_inv[D_N];
__device__ float  g_logdetPsi;
__device__ float  g_r[B_N];
__device__ float  g_Sacc[K_N * 4 * 56];             // per-chunk: 36 S + 8 wm + 8 ns + 1 mm
__device__ float  g_Lp[K_N * 48];                   // [0..35] sqrt(.5)*Linv*al_col, [36..43] wm, [44] off
__device__ float  g_logdetM[K_N];
__device__ float  g_mumu[K_N];
__device__ double g_acc;

__device__ __forceinline__ float softplusf(float x) {
    return x > 20.0f ? x : log1pf(expf(x));
}
__device__ __forceinline__ uint32_t smem_u32(const void* p) {
    uint32_t a;
    asm("{ .reg .u64 t; cvta.to.shared.u64 t, %1; cvt.u32.u64 %0, t; }" : "=r"(a) : "l"(p));
    return a;
}
__device__ __forceinline__ void cp_async16(uint32_t saddr, const void* gaddr) {
    asm volatile("cp.async.cg.shared.global [%0], [%1], 16;" :: "r"(saddr), "l"(gaddr));
}
__device__ __forceinline__ float warp_sum(float v) {
#pragma unroll
    for (int o = 16; o; o >>= 1) v += __shfl_xor_sync(0xffffffffu, v, o);
    return v;
}

// ---------------- psi precompute ----------------
__global__ void k_psi(const float* __restrict__ psi_rho) {
    __shared__ float ssum;
    int tid = threadIdx.x;
    if (tid == 0) ssum = 0.0f;
    __syncthreads();
    float l = 0.0f;
    for (int d = tid; d < D_N; d += 1024) {
        float p = softplusf(psi_rho[d]) + EPSC;
        g_psi_inv[d] = 1.0f / p;
        l += logf(p);
    }
    l = warp_sum(l);
    if ((tid & 31) == 0) atomicAdd(&ssum, l);
    __syncthreads();
    if (tid == 0) g_logdetPsi = ssum;
}

// ---------------- X -> bf16 ----------------
__global__ void k_cvt(const float* __restrict__ x) {
    size_t i = ((size_t)blockIdx.x * 256 + threadIdx.x) * 8;
    float4 a = *(const float4*)(x + i);
    float4 b = *(const float4*)(x + i + 4);
    __nv_bfloat162 p0 = __float22bfloat162_rn(make_float2(a.x, a.y));
    __nv_bfloat162 p1 = __float22bfloat162_rn(make_float2(a.z, a.w));
    __nv_bfloat162 p2 = __float22bfloat162_rn(make_float2(b.x, b.y));
    __nv_bfloat162 p3 = __float22bfloat162_rn(make_float2(b.z, b.w));
    uint4 o;
    o.x = *(uint32_t*)&p0; o.y = *(uint32_t*)&p1;
    o.z = *(uint32_t*)&p2; o.w = *(uint32_t*)&p3;
    *(uint4*)(g_XB + i) = o;
}

// ---------------- pB: ALL per-k stats (S, wm, ns, mm) + Wcat writes ---------
__global__ void pB(const float* __restrict__ dir_raw,
                   const float* __restrict__ mu) {
    int k = blockIdx.y, chunk = blockIdx.x, tid = threadIdx.x, lane = tid & 31;
    __shared__ float s_acc[53];
    if (tid < 53) s_acc[tid] = 0.0f;
    __syncthreads();

    const float* dirk = dir_raw + (size_t)k * D_N * Q_N;
    const float* muk  = mu + (size_t)k * D_N;

    float S[36], wm[8], ns[8], mm = 0.0f;
#pragma unroll
    for (int i = 0; i < 36; i++) S[i] = 0.0f;
#pragma unroll
    for (int i = 0; i < 8; i++) { wm[i] = 0.0f; ns[i] = 0.0f; }

    int d0 = chunk * 512;
#pragma unroll
    for (int it = 0; it < 2; it++) {
        int d = d0 + tid + it * 256;
        float dv[8];
        float4 a  = *(const float4*)(dirk + (size_t)d * 8);
        float4 b4 = *(const float4*)(dirk + (size_t)d * 8 + 4);
        dv[0] = a.x; dv[1] = a.y; dv[2] = a.z; dv[3] = a.w;
        dv[4] = b4.x; dv[5] = b4.y; dv[6] = b4.z; dv[7] = b4.w;
        float pi = g_psi_inv[d];
        float m  = muk[d];
        float pim = pi * m;
        mm += m * pim;
        int idx = 0;
#pragma unroll
        for (int i = 0; i < 8; i++) {
            float pdi = pi * dv[i];
            wm[i] += m * pdi;
            ns[i] += dv[i] * dv[i];
#pragma unroll
            for (int j = 0; j <= i; j++) S[idx++] += pdi * dv[j];
        }
        g_WB[(size_t)k * D_N + d] = __float2bfloat16(pim);
#pragma unroll
        for (int j = 0; j < 8; j++)
            g_WB[(size_t)(K_N + k * 8 + j) * D_N + d] = __float2bfloat16(pi * dv[j]);
    }
#pragma unroll
    for (int i = 0; i < 36; i++) {
        S[i] = warp_sum(S[i]);
        if (lane == 0) atomicAdd(&s_acc[i], S[i]);
    }
#pragma unroll
    for (int j = 0; j < 8; j++) {
        wm[j] = warp_sum(wm[j]);
        if (lane == 0) atomicAdd(&s_acc[36 + j], wm[j]);
        ns[j] = warp_sum(ns[j]);
        if (lane == 0) atomicAdd(&s_acc[44 + j], ns[j]);
    }
    mm = warp_sum(mm);
    if (lane == 0) atomicAdd(&s_acc[52], mm);
    __syncthreads();
    if (tid < 53) g_Sacc[(size_t)(k * 4 + chunk) * 56 + tid] = s_acc[tid];
}

// ---------------- bf16 MMA GEMM: 4-stage, 1 barrier per kb ------------------
#define BK       32
#define KBLOCKS  (D_N / BK)      // 64
#define STAGES   4
#define TILE_A   8192
#define TILE_B   8192
#define TILE_AB  (TILE_A + TILE_B)
#define GEMM_SMEM (STAGES * TILE_AB)   // 64 KB

__global__ void __launch_bounds__(256, 2) k_mma_gemm() {
    extern __shared__ __align__(128) char smem[];
    const int tid  = threadIdx.x;
    const int wid  = tid >> 5;
    const int lane = tid & 31;
    const int warp_m = wid & 1;    // 2 x 64 rows
    const int warp_n = wid >> 1;   // 4 x 32 cols
    const int bx = blockIdx.x;     // 0..35 (bx<4 -> t1 region, else v region)
    const int by = blockIdx.y;     // 0..63

    const uint32_t sbase = smem_u32(smem);
    const __nv_bfloat16* Ag = g_XB + (size_t)(by * 128) * D_N;
    const __nv_bfloat16* Bg = g_WB + (size_t)(bx * 128) * D_N;

    auto load_stage = [&](int s, int kb) {
        uint32_t aB = sbase + s * TILE_AB;
        uint32_t bB = aB + TILE_A;
#pragma unroll
        for (int i = 0; i < 2; i++) {
            int id  = tid + i * 256;
            int row = id >> 2;
            int ch  = id & 3;
            int sw  = ch ^ ((row >> 1) & 3);
            cp_async16(aB + row * 64 + sw * 16, Ag + (size_t)row * D_N + kb * BK + ch * 8);
            cp_async16(bB + row * 64 + sw * 16, Bg + (size_t)row * D_N + kb * BK + ch * 8);
        }
        asm volatile("cp.async.commit_group;");
    };

    float acc[4][4][4];
#pragma unroll
    for (int mi = 0; mi < 4; mi++)
#pragma unroll
        for (int ni = 0; ni < 4; ni++)
#pragma unroll
            for (int j = 0; j < 4; j++) acc[mi][ni][j] = 0.0f;

    load_stage(0, 0);
    load_stage(1, 1);
    load_stage(2, 2);

    for (int kb = 0; kb < KBLOCKS; kb++) {
        if (kb + 2 < KBLOCKS)       asm volatile("cp.async.wait_group 2;");
        else if (kb + 2 == KBLOCKS) asm volatile("cp.async.wait_group 1;");
        else                        asm volatile("cp.async.wait_group 0;");
        __syncthreads();
        if (kb + 3 < KBLOCKS) load_stage((kb + 3) & 3, kb + 3);
        uint32_t aB = sbase + (kb & 3) * TILE_AB;
        uint32_t bB = aB + TILE_A;
#pragma unroll
        for (int ks = 0; ks < 2; ks++) {
            uint32_t a[4][4], b[4][2];
#pragma unroll
            for (int mi = 0; mi < 4; mi++) {
                int r  = warp_m * 64 + mi * 16 + (lane & 15);
                int ch = ks * 2 + (lane >> 4);
                uint32_t ad = aB + r * 64 + ((ch ^ ((r >> 1) & 3)) << 4);
                asm volatile("ldmatrix.sync.aligned.m8n8.x4.shared.b16 {%0,%1,%2,%3}, [%4];"
                             : "=r"(a[mi][0]), "=r"(a[mi][1]), "=r"(a[mi][2]), "=r"(a[mi][3])
                             : "r"(ad));
            }
#pragma unroll
            for (int p = 0; p < 2; p++) {
                int g  = lane >> 3, rl = lane & 7;
                int r  = warp_n * 32 + p * 16 + (g >> 1) * 8 + rl;
                int ch = ks * 2 + (g & 1);
                uint32_t bd = bB + r * 64 + ((ch ^ ((r >> 1) & 3)) << 4);
                asm volatile("ldmatrix.sync.aligned.m8n8.x4.shared.b16 {%0,%1,%2,%3}, [%4];"
                             : "=r"(b[2 * p][0]), "=r"(b[2 * p][1]),
                               "=r"(b[2 * p + 1][0]), "=r"(b[2 * p + 1][1])
                             : "r"(bd));
            }
#pragma unroll
            for (int mi = 0; mi < 4; mi++)
#pragma unroll
                for (int ni = 0; ni < 4; ni++) {
                    asm volatile(
                        "mma.sync.aligned.m16n8k16.row.col.f32.bf16.bf16.f32 "
                        "{%0,%1,%2,%3}, {%4,%5,%6,%7}, {%8,%9}, {%0,%1,%2,%3};"
                        : "+f"(acc[mi][ni][0]), "+f"(acc[mi][ni][1]),
                          "+f"(acc[mi][ni][2]), "+f"(acc[mi][ni][3])
                        : "r"(a[mi][0]), "r"(a[mi][1]), "r"(a[mi][2]), "r"(a[mi][3]),
                          "r"(b[ni][0]), "r"(b[ni][1]));
                }
        }
        // no trailing barrier: stage (kb+3)&3 was last read at kb-1, protected
        // by the top-of-loop __syncthreads of iteration kb.
    }

    const int gq = lane >> 2;
    const int tg = lane & 3;

    if (bx < 4) {
#pragma unroll
        for (int mi = 0; mi < 4; mi++) {
            int r0 = by * 128 + warp_m * 64 + mi * 16 + gq;
            int r1 = r0 + 8;
#pragma unroll
            for (int ni = 0; ni < 4; ni++) {
                int col = bx * 128 + warp_n * 32 + ni * 8 + tg * 2;
                *(float2*)&g_T[(size_t)r0 * K_N + col] = make_float2(acc[mi][ni][0], acc[mi][ni][1]);
                *(float2*)&g_T[(size_t)r1 * K_N + col] = make_float2(acc[mi][ni][2], acc[mi][ni][3]);
            }
        }
    } else {
#pragma unroll
        for (int mi = 0; mi < 4; mi++) {
            int r0 = by * 128 + warp_m * 64 + mi * 16 + gq;
            int r1 = r0 + 8;
#pragma unroll
            for (int ni = 0; ni < 4; ni++) {
                int col = (bx - 4) * 128 + warp_n * 32 + ni * 8 + tg * 2;
                __nv_bfloat162 lo = __float22bfloat162_rn(make_float2(acc[mi][ni][0], acc[mi][ni][1]));
                __nv_bfloat162 hi = __float22bfloat162_rn(make_float2(acc[mi][ni][2], acc[mi][ni][3]));
                *(__nv_bfloat162*)&g_V[(size_t)r0 * 4096 + col] = lo;
                *(__nv_bfloat162*)&g_V[(size_t)r1 * 4096 + col] = hi;
            }
        }
    }
}

// ---------------- pC: reduce chunks, alpha, Cholesky -> packed Lp -----------
__global__ void pC(const float* __restrict__ scale_rho) {
    int k = blockIdx.x * 128 + threadIdx.x;
    if (k >= K_N) return;
    float buf[53];
    for (int i = 0; i < 53; i++) {
        float s = 0.0f;
        for (int c = 0; c < 4; c++) s += g_Sacc[(size_t)(k * 4 + c) * 56 + i];
        buf[i] = s;
    }
    float al[8];
#pragma unroll
    for (int j = 0; j < 8; j++) {
        float sp = softplusf(scale_rho[k * 8 + j]);
        al[j] = sp / fmaxf(sqrtf(buf[44 + j]), EPSC);
    }

    float Mm[8][8];
    int idx = 0;
    for (int i = 0; i < 8; i++)
        for (int j = 0; j <= i; j++)
            Mm[i][j] = al[i] * al[j] * buf[idx++] + (i == j ? 1.0f : 0.0f);
    for (int i = 0; i < 8; i++) {
        for (int j = 0; j <= i; j++) {
            float s = Mm[i][j];
            for (int p = 0; p < j; p++) s -= Mm[i][p] * Mm[j][p];
            if (i == j) Mm[i][i] = sqrtf(s);
            else        Mm[i][j] = s / Mm[j][j];
        }
    }
    float ld = 0.0f;
    for (int i = 0; i < 8; i++) ld += logf(Mm[i][i]);
    g_logdetM[k] = 2.0f * ld;
    g_mumu[k]    = buf[52];
    for (int j = 0; j < 8; j++) g_Lp[k * 48 + 36 + j] = buf[36 + j];  // wm, no alpha

    float Li[8][8];
    for (int i = 0; i < 8; i++)
        for (int j = 0; j < 8; j++) Li[i][j] = 0.0f;
    for (int c = 0; c < 8; c++) {
        for (int i = c; i < 8; i++) {
            float s = (i == c) ? 1.0f : 0.0f;
            for (int p = c; p < i; p++) s -= Mm[i][p] * Li[p][c];
            Li[i][c] = s / Mm[i][i];
        }
    }
    idx = 0;
    for (int i = 0; i < 8; i++)
        for (int j = 0; j <= i; j++)
            g_Lp[k * 48 + idx++] = 0.70710678118654752f * Li[i][j] * al[j];
}

__global__ void k_init() { g_acc = 0.0; }

// ---------------- per-k offset -> g_Lp[44] ----------------
__global__ void k_off(const float* __restrict__ pi_logits) {
    __shared__ float buf[512];
    int t = threadIdx.x;
    float v = pi_logits[t];
    buf[t] = v;
    __syncthreads();
    for (int s = 256; s > 0; s >>= 1) {
        if (t < s) buf[t] = fmaxf(buf[t], buf[t + s]);
        __syncthreads();
    }
    float mx = buf[0];
    __syncthreads();
    buf[t] = expf(v - mx);
    __syncthreads();
    for (int s = 256; s > 0; s >>= 1) {
        if (t < s) buf[t] += buf[t + s];
        __syncthreads();
    }
    float lse = logf(buf[0]) + mx;
    g_Lp[t * 48 + 44] = -0.5f * ((float)D_N * LOG2PI + g_logdetPsi + g_logdetM[t] + g_mumu[t])
                        + v - lse;
}

// ---------------- r[b] = x^T Psi^-1 x ----------------
__global__ void k_xpx(const float* __restrict__ x) {
    int warp = threadIdx.x >> 5, lane = threadIdx.x & 31;
    int b = blockIdx.x * 8 + warp;
    const float* xb = x + (size_t)b * D_N;
    float s = 0.0f;
    for (int d = lane * 4; d < D_N; d += 128) {
        float4 xv = *(const float4*)(xb + d);
        float4 pv = *(const float4*)(g_psi_inv + d);
        s += xv.x * xv.x * pv.x + xv.y * xv.y * pv.y
           + xv.z * xv.z * pv.z + xv.w * xv.w * pv.w;
    }
    s = warp_sum(s);
    if (lane == 0) g_r[b] = s;
}

// ---------------- fused e1+e2: quad (Cholesky form) + logsumexp + NLL -------
__global__ void __launch_bounds__(256) k_e2() {
    __shared__ float sL[64 * 49];
    int tid = threadIdx.x, warp = tid >> 5, lane = tid & 31;
    int b0 = blockIdx.x * 16 + warp * 2;
    int b1 = b0 + 1;
    const __nv_bfloat16* vr0 = g_V + (size_t)b0 * 4096;
    const __nv_bfloat16* vr1 = g_V + (size_t)b1 * 4096;
    const float* tr0 = g_T + (size_t)b0 * K_N;
    const float* tr1 = g_T + (size_t)b1 * K_N;

    float m0 = -1e30f, s0 = 0.0f, m1 = -1e30f, s1 = 0.0f;
    for (int ch = 0; ch < 8; ch++) {
        int k0 = ch * 64;
        for (int t = tid; t < 64 * 48; t += 256) {
            int kk = t / 48, c = t - kk * 48;
            sL[kk * 49 + c] = g_Lp[(size_t)(k0 + kk) * 48 + c];
        }
        __syncthreads();
#pragma unroll
        for (int half = 0; half < 2; half++) {
            int kl = half * 32 + lane;
            int k  = k0 + kl;
            const float* P = &sL[kl * 49];
#pragma unroll
            for (int bb = 0; bb < 2; bb++) {
                const __nv_bfloat16* vrow = bb ? vr1 : vr0;
                const float*          trow = bb ? tr1 : tr0;
                uint4 raw = *(const uint4*)(vrow + (size_t)k * 8);
                float v[8];
                {
                    float2 f0 = __bfloat1622float2(*(__nv_bfloat162*)&raw.x);
                    float2 f1 = __bfloat1622float2(*(__nv_bfloat162*)&raw.y);
                    float2 f2 = __bfloat1622float2(*(__nv_bfloat162*)&raw.z);
                    float2 f3 = __bfloat1622float2(*(__nv_bfloat162*)&raw.w);
                    v[0] = f0.x; v[1] = f0.y; v[2] = f1.x; v[3] = f1.y;
                    v[4] = f2.x; v[5] = f2.y; v[6] = f3.x; v[7] = f3.y;
                }
#pragma unroll
                for (int j = 0; j < 8; j++) v[j] -= P[36 + j];
                float q = 0.0f;
                int idx = 0;
#pragma unroll
                for (int i = 0; i < 8; i++) {
                    float y = 0.0f;
#pragma unroll
                    for (int j = 0; j <= i; j++) y += P[idx++] * v[j];
                    q += y * y;
                }
                float val = trow[k] + P[44] + q;
                if (bb == 0) {
                    if (val > m0) { s0 = s0 * expf(m0 - val) + 1.0f; m0 = val; }
                    else          { s0 += expf(val - m0); }
                } else {
                    if (val > m1) { s1 = s1 * expf(m1 - val) + 1.0f; m1 = val; }
                    else          { s1 += expf(val - m1); }
                }
            }
        }
        __syncthreads();
    }
#pragma unroll
    for (int o = 16; o; o >>= 1) {
        float mo = __shfl_xor_sync(0xffffffffu, m0, o);
        float so = __shfl_xor_sync(0xffffffffu, s0, o);
        float M = fmaxf(m0, mo);
        s0 = s0 * expf(m0 - M) + so * expf(mo - M);
        m0 = M;
        mo = __shfl_xor_sync(0xffffffffu, m1, o);
        so = __shfl_xor_sync(0xffffffffu, s1, o);
        M = fmaxf(m1, mo);
        s1 = s1 * expf(m1 - M) + so * expf(mo - M);
        m1 = M;
    }
    if (lane == 0) {
        float lp = (logf(s0) + m0 - 0.5f * g_r[b0]) + (logf(s1) + m1 - 0.5f * g_r[b1]);
        atomicAdd(&g_acc, (double)(-lp));
    }
}

__global__ void k_fin(float* out) { out[0] = (float)(g_acc * (1.0 / (double)B_N)); }

// ---------------- launch (GEMM is 4th => gets profiled) ----------------
extern "C" void kernel_launch(void* const* d_in, const int* in_sizes, int n_in,
                              void* d_out, int out_size) {
    const float* x         = (const float*)d_in[0];
    const float* mu        = (const float*)d_in[1];
    const float* dir_raw   = (const float*)d_in[2];
    const float* scale_rho = (const float*)d_in[3];
    const float* psi_rho   = (const float*)d_in[4];
    const float* pi_logits = (const float*)d_in[5];
    float* out = (float*)d_out;

    cudaFuncSetAttribute(k_mma_gemm, cudaFuncAttributeMaxDynamicSharedMemorySize, GEMM_SMEM);

    k_psi<<<1, 1024>>>(psi_rho);                            // 1
    k_cvt<<<(B_N * D_N) / (256 * 8), 256>>>(x);             // 2
    pB<<<dim3(4, K_N), 256>>>(dir_raw, mu);                 // 3
    dim3 gg(36, 64);
    k_mma_gemm<<<gg, 256, GEMM_SMEM>>>();                   // 4  <- profiled
    pC<<<4, 128>>>(scale_rho);                              // 5
    k_init<<<1, 1>>>();                                     // 6
    k_off<<<1, 512>>>(pi_logits);                           // 7
    k_xpx<<<B_N / 8, 256>>>(x);                             // 8
    k_e2<<<B_N / 16, 256>>>();                              // 9
    k_fin<<<1, 1>>>(out);                                   // 10
}